// round 14
// baseline (speedup 1.0000x reference)
#include <cuda_runtime.h>
#include <cuda_bf16.h>
#include <cstdint>

#define NN   50000
#define EE   800000
#define ETOT (EE + NN)
#define DHx  128
#define DOUTx 64
#define NGx  128

// ---------------- device scratch ----------------
__device__ int   g_is64;
__device__ int   g_cnt[NN];
__device__ unsigned int g_aggflag[49];   // scan lookback: 0=not ready, agg+1=ready
__device__ int   g_bnctr;                // last-block counter for BN reduction
__device__ int   g_rowptr[NN + 1];
__device__ int   g_pos[ETOT];            // per-edge rank within its dst row (from hist)
__device__ int   g_ssrc[ETOT];
__device__ float g_xp[NN * DHx];
__device__ float g_h [NN * DHx];
__device__ float g_es[NN];
__device__ float g_ed[NN];
__device__ float g_bsp[512 * 256];   // bnstats per-block partials
__device__ float g_scale[DHx];
__device__ float g_shift[DHx];
__device__ uint4 g_bpk[4096];        // fragment-packed W^T hi/lo

__device__ __forceinline__ uint32_t pack_bf2(float a, float b) {
    __nv_bfloat162 t = __floats2bfloat162_rn(a, b);
    return *(uint32_t*)&t;
}

__device__ __forceinline__ void mma_bf16(float* c, uint32_t a0, uint32_t a1, uint32_t a2,
                                         uint32_t a3, uint32_t b0, uint32_t b1) {
    asm volatile(
        "mma.sync.aligned.m16n8k16.row.col.f32.bf16.bf16.f32 "
        "{%0,%1,%2,%3},{%4,%5,%6,%7},{%8,%9},{%0,%1,%2,%3};"
        : "+f"(c[0]), "+f"(c[1]), "+f"(c[2]), "+f"(c[3])
        : "r"(a0), "r"(a1), "r"(a2), "r"(a3), "r"(b0), "r"(b1));
}

__device__ __forceinline__ int edge_at(const void* ei, int idx) {
    int v;
    if (g_is64) v = (int)((const long long*)ei)[idx];
    else        v = ((const int*)ei)[idx];
    v = v < 0 ? 0 : (v >= NN ? NN - 1 : v);
    return v;
}

// W prep body: transpose + bf16 hi/lo split, fragment-packed
template <int NOUT>
__device__ __forceinline__ void prepw_body(const float* __restrict__ W, int i) {
    if (i >= NOUT * 32) return;
    int n = i >> 5, ks = (i >> 2) & 7, tg = i & 3;
    int ka = ks * 16 + tg * 2;
    int kb = ka + 8;
    float w00 = W[ka * NOUT + n],       w01 = W[(ka + 1) * NOUT + n];
    float w10 = W[kb * NOUT + n],       w11 = W[(kb + 1) * NOUT + n];
    float h00 = __bfloat162float(__float2bfloat16_rn(w00));
    float h01 = __bfloat162float(__float2bfloat16_rn(w01));
    float h10 = __bfloat162float(__float2bfloat16_rn(w10));
    float h11 = __bfloat162float(__float2bfloat16_rn(w11));
    uint4 v;
    v.x = pack_bf2(w00, w01);
    v.y = pack_bf2(w10, w11);
    v.z = pack_bf2(w00 - h00, w01 - h01);
    v.w = pack_bf2(w10 - h10, w11 - h11);
    g_bpk[i] = v;
}

// ---------------- merged setup: detect + zero_cnt + prepw(W1) + zero_pool + flags ---------
__global__ void k_misc1(const unsigned int* __restrict__ ei_raw,
                        const float* __restrict__ W1, float* __restrict__ out_pool) {
    int b = blockIdx.x, t = threadIdx.x;
    if (b == 0) {
        __shared__ unsigned int sh[256];
        unsigned int v = 0;
        for (int i = t; i < 1024; i += 256) v |= ei_raw[2 * i + 1];
        sh[t] = v;
        __syncthreads();
        for (int off = 128; off; off >>= 1) {
            if (t < off) sh[t] |= sh[t + off];
            __syncthreads();
        }
        if (t == 0) g_is64 = (sh[0] == 0) ? 1 : 0;
    } else if (b <= 196) {
        int i = (b - 1) * 256 + t;
        if (i < NN) g_cnt[i] = 0;
    } else if (b <= 212) {
        prepw_body<128>(W1, (b - 197) * 256 + t);
    } else if (b <= 244) {
        int i = (b - 213) * 256 + t;
        if (i < NGx * DOUTx) out_pool[i] = 0.f;
    } else {
        if (t < 49) g_aggflag[t] = 0u;
        if (t == 49) g_bnctr = 0;
    }
}

// ---------------- CSR build ----------------
// hist also records each edge's rank within its destination row
__global__ void k_hist(const void* __restrict__ ei) {
    int e = blockIdx.x * blockDim.x + threadIdx.x;
    if (e >= ETOT) return;
    int dst = (e < EE) ? edge_at(ei, EE + e) : (e - EE);
    g_pos[e] = atomicAdd(&g_cnt[dst], 1);
}

// single-pass scan with decoupled lookback (49 blocks x 1024)
__global__ void k_scan_fused() {
    int t = threadIdx.x, b = blockIdx.x;
    int i = b * 1024 + t;
    int v = (i < NN) ? g_cnt[i] : 0;
    __shared__ int sh[1024];
    sh[t] = v;
    __syncthreads();
    for (int off = 1; off < 1024; off <<= 1) {
        int a = (t >= off) ? sh[t - off] : 0;
        __syncthreads();
        sh[t] += a;
        __syncthreads();
    }
    int excl  = sh[t] - v;        // local exclusive prefix
    int total = sh[1023];         // block aggregate
    __syncthreads();

    if (t == 0) {
        __threadfence();
        atomicExch(&g_aggflag[b], (unsigned int)(total + 1));
    }

    int pv = 0;
    if (t < b) {
        unsigned int u;
        do { u = atomicAdd(&g_aggflag[t], 0u); } while (u == 0u);
        pv = (int)u - 1;
    }
    sh[t] = pv;
    __syncthreads();
    for (int off = 512; off; off >>= 1) {
        if (t < off) sh[t] += sh[t + off];
        __syncthreads();
    }
    int prefix = sh[0];

    if (i < NN) g_rowptr[i] = prefix + excl;
    if (b == 0 && t == 0) g_rowptr[NN] = ETOT;
}

// atomic-free scatter: position = rowptr[dst] + rank
__global__ void k_scatter(const void* __restrict__ ei) {
    int e = blockIdx.x * blockDim.x + threadIdx.x;
    if (e >= ETOT) return;
    int s, d;
    if (e < EE) { s = edge_at(ei, e); d = edge_at(ei, EE + e); }
    else        { s = e - EE;         d = s; }
    g_ssrc[g_rowptr[d] + g_pos[e]] = s;
}

// ---------------- warp-MMA GEMM: 64 x NOUT tile, K=128, 3-term bf16 split --------
template <int NOUT, bool BN>
__global__ void __launch_bounds__(256, 3) k_gemm_mma(const float* __restrict__ A,
                                                     const float* __restrict__ asv,
                                                     const float* __restrict__ adv, int n) {
    extern __shared__ char smem[];
    const float* __restrict__ Ap = BN ? (const float*)g_h : A;
    constexpr int RSTR = 576;
    float* sas = (float*)(smem);
    float* sad = (float*)(smem + 512);
    float* sc  = (float*)(smem + 1024);
    float* sf  = (float*)(smem + 1536);
    float* esp = (float*)(smem + 2048);
    float* edp = (float*)(smem + 3072);
    char*  ap  = smem + 4096;

    int tid = threadIdx.x, wid = tid >> 5, lane = tid & 31;
    int r0 = blockIdx.x * 64;

    if (tid < NOUT) { sas[tid] = asv[tid]; sad[tid] = adv[tid]; }
    if (BN && tid < 128) { sc[tid] = g_scale[tid]; sf[tid] = g_shift[tid]; }
    if (BN) __syncthreads();

    for (int l = tid; l < 64 * 32; l += 256) {
        int row = l >> 5, ks = (l >> 2) & 7, tg = l & 3;
        int ka = ks * 16 + tg * 2;
        int kb = ka + 8;
        float a0 = 0.f, a1 = 0.f, b0 = 0.f, b1 = 0.f;
        if (r0 + row < n) {
            float2 t = *(const float2*)&Ap[(r0 + row) * 128 + ka];
            a0 = t.x; a1 = t.y;
            float2 u = *(const float2*)&Ap[(r0 + row) * 128 + kb];
            b0 = u.x; b1 = u.y;
        }
        if (BN) {
            a0 = fmaxf(a0 * sc[ka] + sf[ka], 0.f);
            a1 = fmaxf(a1 * sc[ka + 1] + sf[ka + 1], 0.f);
            b0 = fmaxf(b0 * sc[kb] + sf[kb], 0.f);
            b1 = fmaxf(b1 * sc[kb + 1] + sf[kb + 1], 0.f);
        }
        float h0 = __bfloat162float(__float2bfloat16_rn(a0));
        float h1 = __bfloat162float(__float2bfloat16_rn(a1));
        float h2 = __bfloat162float(__float2bfloat16_rn(b0));
        float h3 = __bfloat162float(__float2bfloat16_rn(b1));
        uint4 v;
        v.x = pack_bf2(a0, a1);
        v.y = pack_bf2(b0, b1);
        v.z = pack_bf2(a0 - h0, a1 - h1);
        v.w = pack_bf2(b0 - h2, b1 - h3);
        *(uint4*)(ap + row * RSTR + ks * 64 + tg * 16) = v;
    }
    __syncthreads();

    constexpr int WN = (NOUT == 128) ? 32 : 16;
    constexpr int NA = WN / 8;
    int wm = (wid & 1) * 32;
    int wn = (wid >> 1) * WN;
    int gq = lane >> 2, tg = lane & 3, t2 = tg * 2;

    float acc[2][NA][4];
#pragma unroll
    for (int i = 0; i < 2; i++)
#pragma unroll
        for (int j = 0; j < NA; j++)
#pragma unroll
            for (int q = 0; q < 4; q++) acc[i][j][q] = 0.f;

#pragma unroll
    for (int ks = 0; ks < 8; ks++) {
        uint32_t fbh[NA][2], fbl[NA][2];
#pragma unroll
        for (int j = 0; j < NA; j++) {
            uint4 bv = g_bpk[(wn + j * 8 + gq) * 32 + ks * 4 + tg];
            fbh[j][0] = bv.x; fbh[j][1] = bv.y;
            fbl[j][0] = bv.z; fbl[j][1] = bv.w;
        }
#pragma unroll
        for (int i = 0; i < 2; i++) {
            int rl = wm + i * 16 + gq;
            uint4 av = *(uint4*)(ap + rl * RSTR + ks * 64 + tg * 16);
            uint4 aw = *(uint4*)(ap + (rl + 8) * RSTR + ks * 64 + tg * 16);
#pragma unroll
            for (int j = 0; j < NA; j++) {
                mma_bf16(acc[i][j], av.x, aw.x, av.y, aw.y, fbh[j][0], fbh[j][1]);
                mma_bf16(acc[i][j], av.x, aw.x, av.y, aw.y, fbl[j][0], fbl[j][1]);
                mma_bf16(acc[i][j], av.z, aw.z, av.w, aw.w, fbh[j][0], fbh[j][1]);
            }
        }
    }

    int wng = wid >> 1;
#pragma unroll
    for (int i = 0; i < 2; i++) {
        int rl = r0 + wm + i * 16 + gq;
        int rh = rl + 8;
        float psl = 0.f, pdl = 0.f, psh = 0.f, pdh = 0.f;
#pragma unroll
        for (int j = 0; j < NA; j++) {
            int c0 = wn + j * 8 + t2;
            if (rl < n) *(float2*)&g_xp[rl * NOUT + c0] = make_float2(acc[i][j][0], acc[i][j][1]);
            if (rh < n) *(float2*)&g_xp[rh * NOUT + c0] = make_float2(acc[i][j][2], acc[i][j][3]);
            float s0 = sas[c0], s1 = sas[c0 + 1], d0 = sad[c0], d1 = sad[c0 + 1];
            psl += acc[i][j][0] * s0 + acc[i][j][1] * s1;
            pdl += acc[i][j][0] * d0 + acc[i][j][1] * d1;
            psh += acc[i][j][2] * s0 + acc[i][j][3] * s1;
            pdh += acc[i][j][2] * d0 + acc[i][j][3] * d1;
        }
#pragma unroll
        for (int off = 1; off < 4; off <<= 1) {
            psl += __shfl_xor_sync(0xffffffffu, psl, off);
            pdl += __shfl_xor_sync(0xffffffffu, pdl, off);
            psh += __shfl_xor_sync(0xffffffffu, psh, off);
            pdh += __shfl_xor_sync(0xffffffffu, pdh, off);
        }
        if ((lane & 3) == 0) {
            int rowl = wm + i * 16 + gq;
            esp[wng * 64 + rowl] = psl;       edp[wng * 64 + rowl] = pdl;
            esp[wng * 64 + rowl + 8] = psh;   edp[wng * 64 + rowl + 8] = pdh;
        }
    }
    __syncthreads();
    if (tid < 64) {
        int r = r0 + tid;
        if (r < n) {
            g_es[r] = esp[tid] + esp[64 + tid] + esp[128 + tid] + esp[192 + tid];
            g_ed[r] = edp[tid] + edp[64 + tid] + edp[128 + tid] + edp[192 + tid];
        }
    }
}

// ---------------- GAT aggregation: one WARP per destination node ----------------
template <int C>
__global__ void k_agg(const float* __restrict__ bias, float* __restrict__ out) {
    float* __restrict__ outp = out ? out : (float*)g_h;
    int node = (blockIdx.x * blockDim.x + threadIdx.x) >> 5;
    int lane = threadIdx.x & 31;
    if (node >= NN) return;
    int beg = g_rowptr[node], end = g_rowptr[node + 1];
    int deg = end - beg;
    float edv = g_ed[node];

    constexpr int V = C / 32;
    float acc[V];
#pragma unroll
    for (int v = 0; v < V; v++) acc[v] = 0.f;
    float dp;

    if (deg <= 32) {
        int p = beg + lane;
        int s = 0;
        float al = -3.4e38f;
        if (p < end) {
            s = g_ssrc[p];
            float t = g_es[s] + edv;
            al = t > 0.f ? t : 0.2f * t;
        }
        float m = al;
#pragma unroll
        for (int off = 16; off; off >>= 1) m = fmaxf(m, __shfl_xor_sync(0xffffffffu, m, off));
        float w = (p < end) ? __expf(al - m) : 0.f;
        dp = w;
#pragma unroll
        for (int off = 16; off; off >>= 1) dp += __shfl_xor_sync(0xffffffffu, dp, off);

#pragma unroll 8
        for (int j = 0; j < deg; j++) {
            float wj = __shfl_sync(0xffffffffu, w, j);
            int   sj = __shfl_sync(0xffffffffu, s, j);
            if (V == 4) {
                float4 xv = *(const float4*)&g_xp[sj * C + lane * 4];
                acc[0] += wj * xv.x; acc[1] += wj * xv.y;
                acc[2] += wj * xv.z; acc[3] += wj * xv.w;
            } else {
                float2 xv = *(const float2*)&g_xp[sj * C + lane * 2];
                acc[0] += wj * xv.x; acc[1] += wj * xv.y;
            }
        }
    } else {
        float m = -3.4e38f;
        for (int p = beg + lane; p < end; p += 32) {
            float al = g_es[g_ssrc[p]] + edv;
            al = al > 0.f ? al : 0.2f * al;
            m = fmaxf(m, al);
        }
#pragma unroll
        for (int off = 16; off; off >>= 1) m = fmaxf(m, __shfl_xor_sync(0xffffffffu, m, off));

        dp = 0.f;
        for (int base = beg; base < end; base += 32) {
            int p = base + lane;
            float w = 0.f; int s = 0;
            if (p < end) {
                s = g_ssrc[p];
                float al = g_es[s] + edv;
                al = al > 0.f ? al : 0.2f * al;
                w = __expf(al - m);
                dp += w;
            }
            int cnt = min(32, end - base);
#pragma unroll 4
            for (int j = 0; j < cnt; j++) {
                float wj = __shfl_sync(0xffffffffu, w, j);
                int   sj = __shfl_sync(0xffffffffu, s, j);
                if (V == 4) {
                    float4 xv = *(const float4*)&g_xp[sj * C + lane * 4];
                    acc[0] += wj * xv.x; acc[1] += wj * xv.y;
                    acc[2] += wj * xv.z; acc[3] += wj * xv.w;
                } else {
                    float2 xv = *(const float2*)&g_xp[sj * C + lane * 2];
                    acc[0] += wj * xv.x; acc[1] += wj * xv.y;
                }
            }
        }
#pragma unroll
        for (int off = 16; off; off >>= 1) dp += __shfl_xor_sync(0xffffffffu, dp, off);
    }

    float inv = 1.f / dp;
    if (V == 4) {
        float4 b4 = *(const float4*)&bias[lane * 4];
        float4 o = make_float4(acc[0] * inv + b4.x, acc[1] * inv + b4.y,
                               acc[2] * inv + b4.z, acc[3] * inv + b4.w);
        *(float4*)&outp[node * C + lane * 4] = o;
    } else {
        float2 b2 = *(const float2*)&bias[lane * 2];
        float2 o = make_float2(acc[0] * inv + b2.x, acc[1] * inv + b2.y);
        *(float2*)&outp[node * C + lane * 2] = o;
    }
}

// ---------------- fused BN: stats partials + prepw(next W) + last-block reduction ------
template <int NOUT_NEXT>
__global__ void k_bn_fused(const float* __restrict__ g, const float* __restrict__ be,
                           const float* __restrict__ Wn, int n) {
    int b = blockIdx.x, c = threadIdx.x;

    int pitem = b * 128 + c;
    if (pitem < NOUT_NEXT * 32) prepw_body<NOUT_NEXT>(Wn, pitem);

    float s = 0.f, sq = 0.f;
    for (int r = b; r < n; r += 512) {
        float v = g_h[r * 128 + c];
        s += v; sq += v * v;
    }
    g_bsp[b * 256 + c] = s;
    g_bsp[b * 256 + 128 + c] = sq;

    __threadfence();
    __shared__ int lastflag;
    if (c == 0) lastflag = (atomicAdd(&g_bnctr, 1) == 511) ? 1 : 0;
    __syncthreads();
    if (lastflag) {
        float ts = 0.f, tq = 0.f;
        for (int bb = 0; bb < 512; bb++) {
            ts += g_bsp[bb * 256 + c];
            tq += g_bsp[bb * 256 + 128 + c];
        }
        float inv_n = 1.f / (float)n;
        float m = ts * inv_n;
        float v = tq * inv_n - m * m;
        float scv = g[c] * rsqrtf(v + 1e-5f);
        g_scale[c] = scv;
        g_shift[c] = be[c] - m * scv;
        if (c == 0) g_bnctr = 0;
    }
}

// ---------------- pooling ----------------
__global__ void k_pool(const float* __restrict__ gp, const float* __restrict__ hn,
                       float* __restrict__ outp, int n) {
    __shared__ float gpt[32][129];
    __shared__ float hnt[32][65];
    int tid = threadIdx.x;
    int tn = (tid & 15) * 4;
    int tm = (tid >> 4) * 8;
    float acc[8][4];
#pragma unroll
    for (int a = 0; a < 8; a++)
#pragma unroll
        for (int b = 0; b < 4; b++) acc[a][b] = 0.f;

    int kpb  = (n + gridDim.x - 1) / gridDim.x;
    int kbeg = blockIdx.x * kpb;
    int kend = min(n, kbeg + kpb);

    for (int k0 = kbeg; k0 < kend; k0 += 32) {
        int kt = min(32, kend - k0);
        for (int l = tid; l < 128 * 32; l += 256) {
            int m = l >> 5, kk = l & 31;
            gpt[kk][m] = (kk < kt) ? gp[m * n + k0 + kk] : 0.f;
        }
        for (int l = tid; l < 32 * 64; l += 256) {
            int kk = l >> 6, cc = l & 63;
            hnt[kk][cc] = (kk < kt) ? hn[(k0 + kk) * 64 + cc] : 0.f;
        }
        __syncthreads();
#pragma unroll 4
        for (int kk = 0; kk < 32; kk++) {
            float h0 = hnt[kk][tn + 0], h1 = hnt[kk][tn + 1];
            float h2 = hnt[kk][tn + 2], h3 = hnt[kk][tn + 3];
#pragma unroll
            for (int a = 0; a < 8; a++) {
                float g = gpt[kk][tm + a];
                acc[a][0] += g * h0;
                acc[a][1] += g * h1;
                acc[a][2] += g * h2;
                acc[a][3] += g * h3;
            }
        }
        __syncthreads();
    }
#pragma unroll
    for (int a = 0; a < 8; a++)
#pragma unroll
        for (int b = 0; b < 4; b++)
            atomicAdd(&outp[(tm + a) * 64 + tn + b], acc[a][b]);
}

// ---------------- launch ----------------
extern "C" void kernel_launch(void* const* d_in, const int* in_sizes, int n_in,
                              void* d_out, int out_size) {
    const float* x   = (const float*)d_in[0];
    const void*  ei  = (const void*)d_in[1];
    const float* gp  = (const float*)d_in[2];
    const float* W1  = (const float*)d_in[3];
    const float* as1 = (const float*)d_in[4];
    const float* ad1 = (const float*)d_in[5];
    const float* b1  = (const float*)d_in[6];
    const float* g1  = (const float*)d_in[7];
    const float* be1 = (const float*)d_in[8];
    const float* W2  = (const float*)d_in[9];
    const float* as2 = (const float*)d_in[10];
    const float* ad2 = (const float*)d_in[11];
    const float* b2  = (const float*)d_in[12];
    const float* g2  = (const float*)d_in[13];
    const float* be2 = (const float*)d_in[14];
    const float* W3  = (const float*)d_in[15];
    const float* as3 = (const float*)d_in[16];
    const float* ad3 = (const float*)d_in[17];
    const float* b3  = (const float*)d_in[18];

    float* out       = (float*)d_out;
    float* out_pool  = out;                    // [128,64]
    float* out_nodes = out + NGx * DOUTx;      // [50000,64]

    const int T = 256;
    const int SMA = 4096 + 64 * 576;           // 40960

    int gemm_blocks = (NN + 63) / 64;          // 782
    int warp_blocks = (NN * 32 + T - 1) / T;

    // persistent side stream + events (created once)
    static cudaStream_t s2 = nullptr;
    static cudaEvent_t ev1 = nullptr, ev2 = nullptr;
    if (!s2) {
        cudaStreamCreate(&s2);
        cudaEventCreateWithFlags(&ev1, cudaEventDisableTiming);
        cudaEventCreateWithFlags(&ev2, cudaEventDisableTiming);
    }

    // merged setup (detect + zero_cnt + prepw W1 + zero_pool + flags)
    k_misc1<<<246, 256>>>((const unsigned int*)ei, W1, out_pool);
    cudaEventRecord(ev1, 0);
    cudaStreamWaitEvent(s2, ev1, 0);

    // CSR build on side stream (overlaps GEMM-1)
    k_hist<<<(ETOT + T - 1) / T, T, 0, s2>>>(ei);
    k_scan_fused<<<49, 1024, 0, s2>>>();
    k_scatter<<<(ETOT + T - 1) / T, T, 0, s2>>>(ei);
    cudaEventRecord(ev2, s2);

    // GEMM-1 on main stream, concurrent with CSR
    k_gemm_mma<128, false><<<gemm_blocks, 256, SMA>>>(x, as1, ad1, NN);
    cudaStreamWaitEvent(0, ev2, 0);

    // ---- Layer 1 agg + fused BN ----
    k_agg<128><<<warp_blocks, T>>>(b1, nullptr);
    k_bn_fused<128><<<512, 128>>>(g1, be1, W2, NN);

    // ---- Layer 2 ----
    k_gemm_mma<128, true><<<gemm_blocks, 256, SMA>>>(nullptr, as2, ad2, NN);
    k_agg<128><<<warp_blocks, T>>>(b2, nullptr);
    k_bn_fused<64><<<512, 128>>>(g2, be2, W3, NN);

    // ---- Layer 3 ----
    k_gemm_mma<64, true><<<gemm_blocks, 256, SMA>>>(nullptr, as3, ad3, NN);
    k_agg<64><<<warp_blocks, T>>>(b3, out_nodes);

    // ---- pooling (atomics straight into d_out, zeroed in k_misc1) ----
    k_pool<<<128, 256>>>(gp, out_nodes, out_pool, NN);
}

// round 15
// speedup vs baseline: 1.0629x; 1.0629x over previous
#include <cuda_runtime.h>
#include <cuda_bf16.h>
#include <cuda_fp16.h>
#include <cstdint>

#define NN   50000
#define EE   800000
#define ETOT (EE + NN)
#define DHx  128
#define DOUTx 64
#define NGx  128

// ---------------- device scratch ----------------
__device__ int   g_is64;
__device__ int   g_cnt[NN];
__device__ unsigned int g_aggflag[49];
__device__ int   g_bnctr;
__device__ int   g_rowptr[NN + 1];
__device__ int   g_pos[ETOT];
__device__ int   g_ssrc[ETOT];
__device__ __half g_xph[NN * DHx];   // GEMM output in fp16 (message values only)
__device__ float g_h [NN * DHx];
__device__ float g_es[NN];
__device__ float g_ed[NN];
__device__ float g_bsp[512 * 256];
__device__ float g_scale[DHx];
__device__ float g_shift[DHx];
__device__ uint4 g_bpk[4096];

__device__ __forceinline__ uint32_t pack_bf2(float a, float b) {
    __nv_bfloat162 t = __floats2bfloat162_rn(a, b);
    return *(uint32_t*)&t;
}

__device__ __forceinline__ void mma_bf16(float* c, uint32_t a0, uint32_t a1, uint32_t a2,
                                         uint32_t a3, uint32_t b0, uint32_t b1) {
    asm volatile(
        "mma.sync.aligned.m16n8k16.row.col.f32.bf16.bf16.f32 "
        "{%0,%1,%2,%3},{%4,%5,%6,%7},{%8,%9},{%0,%1,%2,%3};"
        : "+f"(c[0]), "+f"(c[1]), "+f"(c[2]), "+f"(c[3])
        : "r"(a0), "r"(a1), "r"(a2), "r"(a3), "r"(b0), "r"(b1));
}

__device__ __forceinline__ int edge_at(const void* ei, int idx) {
    int v;
    if (g_is64) v = (int)((const long long*)ei)[idx];
    else        v = ((const int*)ei)[idx];
    v = v < 0 ? 0 : (v >= NN ? NN - 1 : v);
    return v;
}

template <int NOUT>
__device__ __forceinline__ void prepw_body(const float* __restrict__ W, int i) {
    if (i >= NOUT * 32) return;
    int n = i >> 5, ks = (i >> 2) & 7, tg = i & 3;
    int ka = ks * 16 + tg * 2;
    int kb = ka + 8;
    float w00 = W[ka * NOUT + n],       w01 = W[(ka + 1) * NOUT + n];
    float w10 = W[kb * NOUT + n],       w11 = W[(kb + 1) * NOUT + n];
    float h00 = __bfloat162float(__float2bfloat16_rn(w00));
    float h01 = __bfloat162float(__float2bfloat16_rn(w01));
    float h10 = __bfloat162float(__float2bfloat16_rn(w10));
    float h11 = __bfloat162float(__float2bfloat16_rn(w11));
    uint4 v;
    v.x = pack_bf2(w00, w01);
    v.y = pack_bf2(w10, w11);
    v.z = pack_bf2(w00 - h00, w01 - h01);
    v.w = pack_bf2(w10 - h10, w11 - h11);
    g_bpk[i] = v;
}

// ---------------- merged setup ----------------
__global__ void k_misc1(const unsigned int* __restrict__ ei_raw,
                        const float* __restrict__ W1, float* __restrict__ out_pool) {
    int b = blockIdx.x, t = threadIdx.x;
    if (b == 0) {
        __shared__ unsigned int sh[256];
        unsigned int v = 0;
        for (int i = t; i < 1024; i += 256) v |= ei_raw[2 * i + 1];
        sh[t] = v;
        __syncthreads();
        for (int off = 128; off; off >>= 1) {
            if (t < off) sh[t] |= sh[t + off];
            __syncthreads();
        }
        if (t == 0) g_is64 = (sh[0] == 0) ? 1 : 0;
    } else if (b <= 196) {
        int i = (b - 1) * 256 + t;
        if (i < NN) g_cnt[i] = 0;
    } else if (b <= 212) {
        prepw_body<128>(W1, (b - 197) * 256 + t);
    } else if (b <= 244) {
        int i = (b - 213) * 256 + t;
        if (i < NGx * DOUTx) out_pool[i] = 0.f;
    } else {
        if (t < 49) g_aggflag[t] = 0u;
        if (t == 49) g_bnctr = 0;
    }
}

// ---------------- CSR build ----------------
__global__ void k_hist(const void* __restrict__ ei) {
    int e = blockIdx.x * blockDim.x + threadIdx.x;
    if (e >= ETOT) return;
    int dst = (e < EE) ? edge_at(ei, EE + e) : (e - EE);
    g_pos[e] = atomicAdd(&g_cnt[dst], 1);
}

__global__ void k_scan_fused() {
    int t = threadIdx.x, b = blockIdx.x;
    int i = b * 1024 + t;
    int v = (i < NN) ? g_cnt[i] : 0;
    __shared__ int sh[1024];
    sh[t] = v;
    __syncthreads();
    for (int off = 1; off < 1024; off <<= 1) {
        int a = (t >= off) ? sh[t - off] : 0;
        __syncthreads();
        sh[t] += a;
        __syncthreads();
    }
    int excl  = sh[t] - v;
    int total = sh[1023];
    __syncthreads();

    if (t == 0) {
        __threadfence();
        atomicExch(&g_aggflag[b], (unsigned int)(total + 1));
    }

    int pv = 0;
    if (t < b) {
        unsigned int u;
        do { u = atomicAdd(&g_aggflag[t], 0u); } while (u == 0u);
        pv = (int)u - 1;
    }
    sh[t] = pv;
    __syncthreads();
    for (int off = 512; off; off >>= 1) {
        if (t < off) sh[t] += sh[t + off];
        __syncthreads();
    }
    int prefix = sh[0];

    if (i < NN) g_rowptr[i] = prefix + excl;
    if (b == 0 && t == 0) g_rowptr[NN] = ETOT;
}

__global__ void k_scatter(const void* __restrict__ ei) {
    int e = blockIdx.x * blockDim.x + threadIdx.x;
    if (e >= ETOT) return;
    int s, d;
    if (e < EE) { s = edge_at(ei, e); d = edge_at(ei, EE + e); }
    else        { s = e - EE;         d = s; }
    g_ssrc[g_rowptr[d] + g_pos[e]] = s;
}

// ---------------- warp-MMA GEMM: 64 x NOUT tile, K=128, 3-term bf16 split --------
// output xp stored as fp16 (message values); es/ed from fp32 accumulators
template <int NOUT, bool BN>
__global__ void __launch_bounds__(256, 3) k_gemm_mma(const float* __restrict__ A,
                                                     const float* __restrict__ asv,
                                                     const float* __restrict__ adv, int n) {
    extern __shared__ char smem[];
    const float* __restrict__ Ap = BN ? (const float*)g_h : A;
    constexpr int RSTR = 576;
    float* sas = (float*)(smem);
    float* sad = (float*)(smem + 512);
    float* sc  = (float*)(smem + 1024);
    float* sf  = (float*)(smem + 1536);
    float* esp = (float*)(smem + 2048);
    float* edp = (float*)(smem + 3072);
    char*  ap  = smem + 4096;

    int tid = threadIdx.x, wid = tid >> 5, lane = tid & 31;
    int r0 = blockIdx.x * 64;

    if (tid < NOUT) { sas[tid] = asv[tid]; sad[tid] = adv[tid]; }
    if (BN && tid < 128) { sc[tid] = g_scale[tid]; sf[tid] = g_shift[tid]; }
    if (BN) __syncthreads();

    for (int l = tid; l < 64 * 32; l += 256) {
        int row = l >> 5, ks = (l >> 2) & 7, tg = l & 3;
        int ka = ks * 16 + tg * 2;
        int kb = ka + 8;
        float a0 = 0.f, a1 = 0.f, b0 = 0.f, b1 = 0.f;
        if (r0 + row < n) {
            float2 t = *(const float2*)&Ap[(r0 + row) * 128 + ka];
            a0 = t.x; a1 = t.y;
            float2 u = *(const float2*)&Ap[(r0 + row) * 128 + kb];
            b0 = u.x; b1 = u.y;
        }
        if (BN) {
            a0 = fmaxf(a0 * sc[ka] + sf[ka], 0.f);
            a1 = fmaxf(a1 * sc[ka + 1] + sf[ka + 1], 0.f);
            b0 = fmaxf(b0 * sc[kb] + sf[kb], 0.f);
            b1 = fmaxf(b1 * sc[kb + 1] + sf[kb + 1], 0.f);
        }
        float h0 = __bfloat162float(__float2bfloat16_rn(a0));
        float h1 = __bfloat162float(__float2bfloat16_rn(a1));
        float h2 = __bfloat162float(__float2bfloat16_rn(b0));
        float h3 = __bfloat162float(__float2bfloat16_rn(b1));
        uint4 v;
        v.x = pack_bf2(a0, a1);
        v.y = pack_bf2(b0, b1);
        v.z = pack_bf2(a0 - h0, a1 - h1);
        v.w = pack_bf2(b0 - h2, b1 - h3);
        *(uint4*)(ap + row * RSTR + ks * 64 + tg * 16) = v;
    }
    __syncthreads();

    constexpr int WN = (NOUT == 128) ? 32 : 16;
    constexpr int NA = WN / 8;
    int wm = (wid & 1) * 32;
    int wn = (wid >> 1) * WN;
    int gq = lane >> 2, tg = lane & 3, t2 = tg * 2;

    float acc[2][NA][4];
#pragma unroll
    for (int i = 0; i < 2; i++)
#pragma unroll
        for (int j = 0; j < NA; j++)
#pragma unroll
            for (int q = 0; q < 4; q++) acc[i][j][q] = 0.f;

#pragma unroll
    for (int ks = 0; ks < 8; ks++) {
        uint32_t fbh[NA][2], fbl[NA][2];
#pragma unroll
        for (int j = 0; j < NA; j++) {
            uint4 bv = g_bpk[(wn + j * 8 + gq) * 32 + ks * 4 + tg];
            fbh[j][0] = bv.x; fbh[j][1] = bv.y;
            fbl[j][0] = bv.z; fbl[j][1] = bv.w;
        }
#pragma unroll
        for (int i = 0; i < 2; i++) {
            int rl = wm + i * 16 + gq;
            uint4 av = *(uint4*)(ap + rl * RSTR + ks * 64 + tg * 16);
            uint4 aw = *(uint4*)(ap + (rl + 8) * RSTR + ks * 64 + tg * 16);
#pragma unroll
            for (int j = 0; j < NA; j++) {
                mma_bf16(acc[i][j], av.x, aw.x, av.y, aw.y, fbh[j][0], fbh[j][1]);
                mma_bf16(acc[i][j], av.x, aw.x, av.y, aw.y, fbl[j][0], fbl[j][1]);
                mma_bf16(acc[i][j], av.z, aw.z, av.w, aw.w, fbh[j][0], fbh[j][1]);
            }
        }
    }

    int wng = wid >> 1;
#pragma unroll
    for (int i = 0; i < 2; i++) {
        int rl = r0 + wm + i * 16 + gq;
        int rh = rl + 8;
        float psl = 0.f, pdl = 0.f, psh = 0.f, pdh = 0.f;
#pragma unroll
        for (int j = 0; j < NA; j++) {
            int c0 = wn + j * 8 + t2;
            if (rl < n) {
                __half2 hv = __floats2half2_rn(acc[i][j][0], acc[i][j][1]);
                *(__half2*)&g_xph[rl * NOUT + c0] = hv;
            }
            if (rh < n) {
                __half2 hv = __floats2half2_rn(acc[i][j][2], acc[i][j][3]);
                *(__half2*)&g_xph[rh * NOUT + c0] = hv;
            }
            float s0 = sas[c0], s1 = sas[c0 + 1], d0 = sad[c0], d1 = sad[c0 + 1];
            psl += acc[i][j][0] * s0 + acc[i][j][1] * s1;
            pdl += acc[i][j][0] * d0 + acc[i][j][1] * d1;
            psh += acc[i][j][2] * s0 + acc[i][j][3] * s1;
            pdh += acc[i][j][2] * d0 + acc[i][j][3] * d1;
        }
#pragma unroll
        for (int off = 1; off < 4; off <<= 1) {
            psl += __shfl_xor_sync(0xffffffffu, psl, off);
            pdl += __shfl_xor_sync(0xffffffffu, pdl, off);
            psh += __shfl_xor_sync(0xffffffffu, psh, off);
            pdh += __shfl_xor_sync(0xffffffffu, pdh, off);
        }
        if ((lane & 3) == 0) {
            int rowl = wm + i * 16 + gq;
            esp[wng * 64 + rowl] = psl;       edp[wng * 64 + rowl] = pdl;
            esp[wng * 64 + rowl + 8] = psh;   edp[wng * 64 + rowl + 8] = pdh;
        }
    }
    __syncthreads();
    if (tid < 64) {
        int r = r0 + tid;
        if (r < n) {
            g_es[r] = esp[tid] + esp[64 + tid] + esp[128 + tid] + esp[192 + tid];
            g_ed[r] = edp[tid] + edp[64 + tid] + edp[128 + tid] + edp[192 + tid];
        }
    }
}

// ---------------- GAT aggregation: one WARP per node; fp16 gathers ----------------
template <int C>
__global__ void k_agg(const float* __restrict__ bias, float* __restrict__ out) {
    float* __restrict__ outp = out ? out : (float*)g_h;
    int node = (blockIdx.x * blockDim.x + threadIdx.x) >> 5;
    int lane = threadIdx.x & 31;
    if (node >= NN) return;
    int beg = g_rowptr[node], end = g_rowptr[node + 1];
    int deg = end - beg;
    float edv = g_ed[node];

    constexpr int V = C / 32;
    float acc[V];
#pragma unroll
    for (int v = 0; v < V; v++) acc[v] = 0.f;
    float dp;

    if (deg <= 32) {
        int p = beg + lane;
        int s = 0;
        float al = -3.4e38f;
        if (p < end) {
            s = g_ssrc[p];
            float t = g_es[s] + edv;
            al = t > 0.f ? t : 0.2f * t;
        }
        float m = al;
#pragma unroll
        for (int off = 16; off; off >>= 1) m = fmaxf(m, __shfl_xor_sync(0xffffffffu, m, off));
        float w = (p < end) ? __expf(al - m) : 0.f;
        dp = w;
#pragma unroll
        for (int off = 16; off; off >>= 1) dp += __shfl_xor_sync(0xffffffffu, dp, off);

#pragma unroll 8
        for (int j = 0; j < deg; j++) {
            float wj = __shfl_sync(0xffffffffu, w, j);
            int   sj = __shfl_sync(0xffffffffu, s, j);
            if (V == 4) {
                uint2 r = *(const uint2*)&g_xph[sj * C + lane * 4];
                float2 f0 = __half22float2(*(__half2*)&r.x);
                float2 f1 = __half22float2(*(__half2*)&r.y);
                acc[0] += wj * f0.x; acc[1] += wj * f0.y;
                acc[2] += wj * f1.x; acc[3] += wj * f1.y;
            } else {
                uint32_t r = *(const uint32_t*)&g_xph[sj * C + lane * 2];
                float2 f0 = __half22float2(*(__half2*)&r);
                acc[0] += wj * f0.x; acc[1] += wj * f0.y;
            }
        }
    } else {
        float m = -3.4e38f;
        for (int p = beg + lane; p < end; p += 32) {
            float al = g_es[g_ssrc[p]] + edv;
            al = al > 0.f ? al : 0.2f * al;
            m = fmaxf(m, al);
        }
#pragma unroll
        for (int off = 16; off; off >>= 1) m = fmaxf(m, __shfl_xor_sync(0xffffffffu, m, off));

        dp = 0.f;
        for (int base = beg; base < end; base += 32) {
            int p = base + lane;
            float w = 0.f; int s = 0;
            if (p < end) {
                s = g_ssrc[p];
                float al = g_es[s] + edv;
                al = al > 0.f ? al : 0.2f * al;
                w = __expf(al - m);
                dp += w;
            }
            int cnt = min(32, end - base);
#pragma unroll 4
            for (int j = 0; j < cnt; j++) {
                float wj = __shfl_sync(0xffffffffu, w, j);
                int   sj = __shfl_sync(0xffffffffu, s, j);
                if (V == 4) {
                    uint2 r = *(const uint2*)&g_xph[sj * C + lane * 4];
                    float2 f0 = __half22float2(*(__half2*)&r.x);
                    float2 f1 = __half22float2(*(__half2*)&r.y);
                    acc[0] += wj * f0.x; acc[1] += wj * f0.y;
                    acc[2] += wj * f1.x; acc[3] += wj * f1.y;
                } else {
                    uint32_t r = *(const uint32_t*)&g_xph[sj * C + lane * 2];
                    float2 f0 = __half22float2(*(__half2*)&r);
                    acc[0] += wj * f0.x; acc[1] += wj * f0.y;
                }
            }
        }
#pragma unroll
        for (int off = 16; off; off >>= 1) dp += __shfl_xor_sync(0xffffffffu, dp, off);
    }

    float inv = 1.f / dp;
    if (V == 4) {
        float4 b4 = *(const float4*)&bias[lane * 4];
        float4 o = make_float4(acc[0] * inv + b4.x, acc[1] * inv + b4.y,
                               acc[2] * inv + b4.z, acc[3] * inv + b4.w);
        *(float4*)&outp[node * C + lane * 4] = o;
    } else {
        float2 b2 = *(const float2*)&bias[lane * 2];
        float2 o = make_float2(acc[0] * inv + b2.x, acc[1] * inv + b2.y);
        *(float2*)&outp[node * C + lane * 2] = o;
    }
}

// ---------------- fused BN: stats partials + prepw(next W) + last-block reduction ------
template <int NOUT_NEXT>
__global__ void k_bn_fused(const float* __restrict__ g, const float* __restrict__ be,
                           const float* __restrict__ Wn, int n) {
    int b = blockIdx.x, c = threadIdx.x;

    int pitem = b * 128 + c;
    if (pitem < NOUT_NEXT * 32) prepw_body<NOUT_NEXT>(Wn, pitem);

    float s = 0.f, sq = 0.f;
    for (int r = b; r < n; r += 512) {
        float v = g_h[r * 128 + c];
        s += v; sq += v * v;
    }
    g_bsp[b * 256 + c] = s;
    g_bsp[b * 256 + 128 + c] = sq;

    __threadfence();
    __shared__ int lastflag;
    if (c == 0) lastflag = (atomicAdd(&g_bnctr, 1) == 511) ? 1 : 0;
    __syncthreads();
    if (lastflag) {
        float ts = 0.f, tq = 0.f;
        for (int bb = 0; bb < 512; bb++) {
            ts += g_bsp[bb * 256 + c];
            tq += g_bsp[bb * 256 + 128 + c];
        }
        float inv_n = 1.f / (float)n;
        float m = ts * inv_n;
        float v = tq * inv_n - m * m;
        float scv = g[c] * rsqrtf(v + 1e-5f);
        g_scale[c] = scv;
        g_shift[c] = be[c] - m * scv;
        if (c == 0) g_bnctr = 0;
    }
}

// ---------------- pooling ----------------
__global__ void k_pool(const float* __restrict__ gp, const float* __restrict__ hn,
                       float* __restrict__ outp, int n) {
    __shared__ float gpt[32][129];
    __shared__ float hnt[32][65];
    int tid = threadIdx.x;
    int tn = (tid & 15) * 4;
    int tm = (tid >> 4) * 8;
    float acc[8][4];
#pragma unroll
    for (int a = 0; a < 8; a++)
#pragma unroll
        for (int b = 0; b < 4; b++) acc[a][b] = 0.f;

    int kpb  = (n + gridDim.x - 1) / gridDim.x;
    int kbeg = blockIdx.x * kpb;
    int kend = min(n, kbeg + kpb);

    for (int k0 = kbeg; k0 < kend; k0 += 32) {
        int kt = min(32, kend - k0);
        for (int l = tid; l < 128 * 32; l += 256) {
            int m = l >> 5, kk = l & 31;
            gpt[kk][m] = (kk < kt) ? gp[m * n + k0 + kk] : 0.f;
        }
        for (int l = tid; l < 32 * 64; l += 256) {
            int kk = l >> 6, cc = l & 63;
            hnt[kk][cc] = (kk < kt) ? hn[(k0 + kk) * 64 + cc] : 0.f;
        }
        __syncthreads();
#pragma unroll 4
        for (int kk = 0; kk < 32; kk++) {
            float h0 = hnt[kk][tn + 0], h1 = hnt[kk][tn + 1];
            float h2 = hnt[kk][tn + 2], h3 = hnt[kk][tn + 3];
#pragma unroll
            for (int a = 0; a < 8; a++) {
                float g = gpt[kk][tm + a];
                acc[a][0] += g * h0;
                acc[a][1] += g * h1;
                acc[a][2] += g * h2;
                acc[a][3] += g * h3;
            }
        }
        __syncthreads();
    }
#pragma unroll
    for (int a = 0; a < 8; a++)
#pragma unroll
        for (int b = 0; b < 4; b++)
            atomicAdd(&outp[(tm + a) * 64 + tn + b], acc[a][b]);
}

// ---------------- launch ----------------
extern "C" void kernel_launch(void* const* d_in, const int* in_sizes, int n_in,
                              void* d_out, int out_size) {
    const float* x   = (const float*)d_in[0];
    const void*  ei  = (const void*)d_in[1];
    const float* gp  = (const float*)d_in[2];
    const float* W1  = (const float*)d_in[3];
    const float* as1 = (const float*)d_in[4];
    const float* ad1 = (const float*)d_in[5];
    const float* b1  = (const float*)d_in[6];
    const float* g1  = (const float*)d_in[7];
    const float* be1 = (const float*)d_in[8];
    const float* W2  = (const float*)d_in[9];
    const float* as2 = (const float*)d_in[10];
    const float* ad2 = (const float*)d_in[11];
    const float* b2  = (const float*)d_in[12];
    const float* g2  = (const float*)d_in[13];
    const float* be2 = (const float*)d_in[14];
    const float* W3  = (const float*)d_in[15];
    const float* as3 = (const float*)d_in[16];
    const float* ad3 = (const float*)d_in[17];
    const float* b3  = (const float*)d_in[18];

    float* out       = (float*)d_out;
    float* out_pool  = out;                    // [128,64]
    float* out_nodes = out + NGx * DOUTx;      // [50000,64]

    const int T = 256;
    const int SMA = 4096 + 64 * 576;           // 40960

    int gemm_blocks = (NN + 63) / 64;          // 782
    int warp_blocks = (NN * 32 + T - 1) / T;

    static cudaStream_t s2 = nullptr;
    static cudaEvent_t ev1 = nullptr, ev2 = nullptr;
    if (!s2) {
        cudaStreamCreate(&s2);
        cudaEventCreateWithFlags(&ev1, cudaEventDisableTiming);
        cudaEventCreateWithFlags(&ev2, cudaEventDisableTiming);
    }

    k_misc1<<<246, 256>>>((const unsigned int*)ei, W1, out_pool);
    cudaEventRecord(ev1, 0);
    cudaStreamWaitEvent(s2, ev1, 0);

    // CSR build on side stream (overlaps GEMM-1)
    k_hist<<<(ETOT + T - 1) / T, T, 0, s2>>>(ei);
    k_scan_fused<<<49, 1024, 0, s2>>>();
    k_scatter<<<(ETOT + T - 1) / T, T, 0, s2>>>(ei);
    cudaEventRecord(ev2, s2);

    // GEMM-1 on main stream, concurrent with CSR
    k_gemm_mma<128, false><<<gemm_blocks, 256, SMA>>>(x, as1, ad1, NN);
    cudaStreamWaitEvent(0, ev2, 0);

    // ---- Layer 1 agg + fused BN ----
    k_agg<128><<<warp_blocks, T>>>(b1, nullptr);
    k_bn_fused<128><<<512, 128>>>(g1, be1, W2, NN);

    // ---- Layer 2 ----
    k_gemm_mma<128, true><<<gemm_blocks, 256, SMA>>>(nullptr, as2, ad2, NN);
    k_agg<128><<<warp_blocks, T>>>(b2, nullptr);
    k_bn_fused<64><<<512, 128>>>(g2, be2, W3, NN);

    // ---- Layer 3 ----
    k_gemm_mma<64, true><<<gemm_blocks, 256, SMA>>>(nullptr, as3, ad3, NN);
    k_agg<64><<<warp_blocks, T>>>(b3, out_nodes);

    // ---- pooling ----
    k_pool<<<128, 256>>>(gp, out_nodes, out_pool, NN);
}